// round 5
// baseline (speedup 1.0000x reference)
#include <cuda_runtime.h>
#include <cstdint>

#define LDA 132
#define THREADS 512
#define ROWS 64

// smem: hs(64) | Bt(64: x/cc/x) | CDw(128: Wf/Uf/U-gates) | EFw(128: child ping+pong / W-gates)
#define SMEM_FLOATS (384*LDA)
#define SMEM_BYTES  (SMEM_FLOATS*4)

__device__ float wbuf[8][128*LDA];   // pre-transposed, pre-rounded tf32 weights [n][k]

__device__ __forceinline__ float tf32r(float v){
    uint32_t u; asm("cvt.rna.tf32.f32 %0, %1;" : "=r"(u) : "f"(v));
    return __uint_as_float(u);
}
__device__ __forceinline__ float sigf(float v){
    float t = __expf(-v);
    return __fdividef(1.0f, 1.0f + t);
}
__device__ __forceinline__ float tanhfast(float v){
    v = fminf(fmaxf(v, -15.0f), 15.0f);
    float t = __expf(-2.0f*v);
    return __fdividef(1.0f - t, 1.0f + t);
}

__device__ __forceinline__ void cpa16(uint32_t s, const float* g){
    asm volatile("cp.async.cg.shared.global [%0], [%1], 16;\n" :: "r"(s), "l"(g));
}
#define CP_COMMIT() asm volatile("cp.async.commit_group;\n" ::: "memory")
#define CP_WAIT(n)  asm volatile("cp.async.wait_group %0;\n" :: "n"(n) : "memory")

template<int R>
__device__ __forceinline__ void cpa_tile(float* dst, const float* __restrict__ src,
                                         int rs, int tid){
    uint32_t base = (uint32_t)__cvta_generic_to_shared(dst);
    #pragma unroll
    for (int i=0;i<R*32/THREADS;i++){
        int e = tid + i*THREADS;
        int row = e >> 5;
        int c4  = (e & 31) * 4;
        cpa16(base + (uint32_t)(row*LDA + c4)*4u, src + (size_t)row*rs + c4);
    }
}

template<int R>
__device__ __forceinline__ void cvt_tile(float* t, int tid){
    #pragma unroll
    for (int i=0;i<R*32/THREADS;i++){
        int e = tid + i*THREADS;
        int row = e >> 5;
        int c4  = (e & 31) * 4;
        float4* p = reinterpret_cast<float4*>(t + row*LDA + c4);
        float4 v = *p;
        v.x=tf32r(v.x); v.y=tf32r(v.y); v.z=tf32r(v.z); v.w=tf32r(v.w);
        *p = v;
    }
}

__device__ __forceinline__ void cvt_child_accum(float* buf, float* hs, int tid){
    #pragma unroll
    for (int i=0;i<64*32/THREADS;i++){
        int e = tid + i*THREADS;
        int row = e >> 5;
        int c4  = (e & 31) * 4;
        float4* p = reinterpret_cast<float4*>(buf + row*LDA + c4);
        float4 v = *p;
        float4* hp = reinterpret_cast<float4*>(hs + row*LDA + c4);
        float4 h = *hp;
        h.x += v.x; h.y += v.y; h.z += v.z; h.w += v.w;
        *hp = h;
        v.x=tf32r(v.x); v.y=tf32r(v.y); v.z=tf32r(v.z); v.w=tf32r(v.w);
        *p = v;
    }
}

__device__ __forceinline__ void mma8(float* c, const uint32_t* a, const uint32_t* b){
    asm volatile(
      "mma.sync.aligned.m16n8k8.row.col.f32.tf32.tf32.f32 "
      "{%0,%1,%2,%3},{%4,%5,%6,%7},{%8,%9},{%0,%1,%2,%3};\n"
      : "+f"(c[0]), "+f"(c[1]), "+f"(c[2]), "+f"(c[3])
      : "r"(a[0]), "r"(a[1]), "r"(a[2]), "r"(a[3]),
        "r"(b[0]), "r"(b[1]));
}

__device__ __forceinline__ void ldsm4(uint32_t* d, uint32_t saddr){
    asm volatile("ldmatrix.sync.aligned.m8n8.x4.shared.b16 {%0,%1,%2,%3}, [%4];\n"
      : "=r"(d[0]),"=r"(d[1]),"=r"(d[2]),"=r"(d[3]) : "r"(saddr));
}

// 64x128x128 tf32 GEMM; 16 warps as 4(m) x 4(n); warp tile 16 x 32.
// A row-major [m][k], B transposed [n][k]; all frags via ldmatrix.
__device__ __forceinline__ void gemm64(float (&acc)[4][4],
                                       const float* __restrict__ As,
                                       const float* __restrict__ Bs,
                                       int lane, int wm, int wn)
{
    uint32_t abase = (uint32_t)__cvta_generic_to_shared(As);
    uint32_t bbase = (uint32_t)__cvta_generic_to_shared(Bs);
    int aRow = wm*16 + (lane&7) + ((lane>>3)&1)*8;
    int aCol = ((lane>>4)&1)*4;
    uint32_t aoff = abase + (uint32_t)(aRow*LDA + aCol)*4u;
    int bRow = wn*32 + (lane&7) + ((lane>>4)&1)*8;
    int bCol = ((lane>>3)&1)*4;
    uint32_t boff = bbase + (uint32_t)(bRow*LDA + bCol)*4u;

    #pragma unroll
    for (int k8=0;k8<16;k8++){
        uint32_t a[4], b[2][4];
        ldsm4(a,    aoff + k8*32u);
        ldsm4(b[0], boff + k8*32u);                 // nt 0,1
        ldsm4(b[1], boff + 16u*LDA*4u + k8*32u);    // nt 2,3
        mma8(acc[0], a, &b[0][0]);
        mma8(acc[1], a, &b[0][2]);
        mma8(acc[2], a, &b[1][0]);
        mma8(acc[3], a, &b[1][2]);
    }
}

#define ZERO_ACC(A) { _Pragma("unroll") for(int _n=0;_n<4;_n++) _Pragma("unroll") for(int _e=0;_e<4;_e++) (A)[_n][_e]=0.0f; }

// ---- prep: transpose + tf32-round all 8 weight matrices into wbuf ------
__global__ void prep_weights(const float* __restrict__ Wf, const float* __restrict__ Uf,
                             const float* __restrict__ Wu, const float* __restrict__ Uu,
                             const float* __restrict__ Wi, const float* __restrict__ Ui,
                             const float* __restrict__ Wo, const float* __restrict__ Uo)
{
    const float* srcs[8] = {Wf,Uf,Wu,Uu,Wi,Ui,Wo,Uo};
    const float* s = srcs[blockIdx.x];
    float* d = wbuf[blockIdx.x];
    for (int i = threadIdx.x; i < 128*128; i += blockDim.x){
        int n = i >> 7, k = i & 127;
        d[n*LDA + k] = tf32r(s[k*128 + n]);      // [n][k], tf32-rounded
    }
}

__global__ void __launch_bounds__(THREADS, 1)
treelstm_kernel(const float* __restrict__ x,
                const float* __restrict__ child_h,
                const float* __restrict__ child_c,
                const float* __restrict__ bi, const float* __restrict__ bo,
                const float* __restrict__ bu, const float* __restrict__ bf,
                float* __restrict__ out, int N)
{
    extern __shared__ float smem[];
    float* hsA  = smem;               // 64 rows : h_sum (fp32 -> tf32)
    float* Bt   = smem + 64*LDA;      // 64 rows : x tile / child_c / x tile
    float* CDw  = smem + 128*LDA;     // 128 rows: Wf / Uf / U-gates
    float* EFw  = smem + 256*LDA;     // 128 rows: child ping+pong / W-gates
    float* bufA = EFw;
    float* bufB = EFw + 64*LDA;

    const int tid  = threadIdx.x;
    const int lane = tid & 31;
    const int g    = lane >> 2;
    const int r    = lane & 3;
    const int wid  = tid >> 5;
    const int wm   = wid & 3;        // 4 m-groups of 16 rows
    const int wn   = wid >> 2;       // 4 n-groups of 32 cols
    const int m0   = blockIdx.x * ROWS;

    float acc [4][4];
    float cacc[4][4];
    float aux [4][4];

    // ---- prologue ------------------------------------------------------
    cpa_tile<64 >(Bt,  x + (size_t)m0*128, 128, tid);
    cpa_tile<128>(CDw, wbuf[0], LDA, tid);                 // Wf (ready-to-use)
    CP_COMMIT();                                           // G1
    cpa_tile<64>(bufA, child_h + ((size_t)m0*8 + 0)*128, 8*128, tid);
    CP_COMMIT();                                           // G2
    cpa_tile<64>(bufB, child_h + ((size_t)m0*8 + 1)*128, 8*128, tid);
    CP_COMMIT();                                           // G3

    #pragma unroll
    for (int i=0;i<64*32/THREADS;i++){
        int e = tid + i*THREADS;
        int row = e>>5, c4=(e&31)*4;
        *reinterpret_cast<float4*>(hsA + row*LDA + c4) = make_float4(0.f,0.f,0.f,0.f);
    }

    CP_WAIT(2); __syncthreads();                           // x + Wf
    cvt_tile<64>(Bt, tid);
    __syncthreads();

    // ---- phase 1: xf = x @ Wf + bf -------------------------------------
    ZERO_ACC(acc);
    gemm64(acc, Bt, CDw, lane, wm, wn);
    __syncthreads();                                       // Bt, CDw free
    cpa_tile<128>(CDw, wbuf[1], LDA, tid);                 // Uf
    CP_COMMIT();                                           // G4

    #pragma unroll
    for (int nt=0;nt<4;nt++){
        int C0 = wn*32 + nt*8 + 2*r;
        float2 bv = *reinterpret_cast<const float2*>(bf + C0);
        aux[nt][0] = acc[nt][0] + bv.x;
        aux[nt][1] = acc[nt][1] + bv.y;
        aux[nt][2] = acc[nt][2] + bv.x;
        aux[nt][3] = acc[nt][3] + bv.y;
        cacc[nt][0]=0.f; cacc[nt][1]=0.f; cacc[nt][2]=0.f; cacc[nt][3]=0.f;
    }

    // ---- phase 2: children ---------------------------------------------
    for (int k=0;k<8;k++){
        float* buf = (k&1) ? bufB : bufA;
        CP_WAIT(0);                                        // ch_k (+Uf at k=0)
        __syncthreads();                                   // (a) prev epilogue done
        cvt_child_accum(buf, hsA, tid);
        cpa_tile<64>(Bt, child_c + ((size_t)m0*8 + k)*128, 8*128, tid);
        CP_COMMIT();
        if (k<7){
            float* nbuf = (k&1) ? bufA : bufB;
            cpa_tile<64>(nbuf, child_h + ((size_t)m0*8 + (k+1))*128, 8*128, tid);
            CP_COMMIT();
        }
        __syncthreads();                                   // (b) cvt visible
        ZERO_ACC(acc);
        gemm64(acc, buf, CDw, lane, wm, wn);
        if (k<7) { CP_WAIT(1); } else { CP_WAIT(0); }      // cc_k done
        __syncthreads();                                   // (c) cc visible
        #pragma unroll
        for (int nt=0;nt<4;nt++){
            int Rr = wm*16 + g;
            int C0 = wn*32 + nt*8 + 2*r;
            float2 c0 = *reinterpret_cast<const float2*>(Bt +  Rr   *LDA + C0);
            float2 c1 = *reinterpret_cast<const float2*>(Bt + (Rr+8)*LDA + C0);
            cacc[nt][0] += sigf(aux[nt][0] + acc[nt][0]) * c0.x;
            cacc[nt][1] += sigf(aux[nt][1] + acc[nt][1]) * c0.y;
            cacc[nt][2] += sigf(aux[nt][2] + acc[nt][2]) * c1.x;
            cacc[nt][3] += sigf(aux[nt][3] + acc[nt][3]) * c1.y;
        }
    }

    __syncthreads();                                       // all bufs free
    cvt_tile<64>(hsA, tid);                                // round h_sum (own elems)
    cpa_tile<64 >(Bt,  x + (size_t)m0*128, 128, tid);      // x reload
    cpa_tile<128>(EFw, wbuf[2], LDA, tid);                 // Wu
    CP_COMMIT();                                           // G: x+Wu
    cpa_tile<128>(CDw, wbuf[3], LDA, tid);                 // Uu
    CP_COMMIT();                                           // G: Uu

    const float* bs[3] = {bu, bi, bo};

    // ---- phase 3: gates u, i, o ----------------------------------------
    for (int gate=0; gate<3; gate++){
        CP_WAIT(1); __syncthreads();                       // W_gate (+x at gate0)
        if (gate==0){ cvt_tile<64>(Bt, tid); __syncthreads(); }
        ZERO_ACC(acc);
        gemm64(acc, Bt, EFw, lane, wm, wn);
        __syncthreads();                                   // EFw free
        if (gate<2){ cpa_tile<128>(EFw, wbuf[4 + 2*gate], LDA, tid); CP_COMMIT(); }

        if (gate<2) { CP_WAIT(1); } else { CP_WAIT(0); }   // U_gate
        __syncthreads();
        gemm64(acc, hsA, CDw, lane, wm, wn);
        __syncthreads();                                   // CDw free
        if (gate<2){ cpa_tile<128>(CDw, wbuf[5 + 2*gate], LDA, tid); CP_COMMIT(); }

        const float* bp = bs[gate];
        #pragma unroll
        for (int nt=0;nt<4;nt++){
            int C0 = wn*32 + nt*8 + 2*r;
            float2 bv = *reinterpret_cast<const float2*>(bp + C0);
            float p0 = acc[nt][0] + bv.x;
            float p1 = acc[nt][1] + bv.y;
            float p2 = acc[nt][2] + bv.x;
            float p3 = acc[nt][3] + bv.y;
            if (gate == 0){
                aux[nt][0] = tanhfast(p0);
                aux[nt][1] = tanhfast(p1);
                aux[nt][2] = tanhfast(p2);
                aux[nt][3] = tanhfast(p3);
            } else if (gate == 1){
                cacc[nt][0] += sigf(p0) * aux[nt][0];
                cacc[nt][1] += sigf(p1) * aux[nt][1];
                cacc[nt][2] += sigf(p2) * aux[nt][2];
                cacc[nt][3] += sigf(p3) * aux[nt][3];
            } else {
                int R0 = m0 + wm*16 + g;
                float c0 = cacc[nt][0], c1 = cacc[nt][1];
                float c2 = cacc[nt][2], c3 = cacc[nt][3];
                float h0 = sigf(p0) * tanhfast(c0);
                float h1 = sigf(p1) * tanhfast(c1);
                float h2 = sigf(p2) * tanhfast(c2);
                float h3 = sigf(p3) * tanhfast(c3);
                float* outh = out;
                float* outc = out + (size_t)N*128;
                *reinterpret_cast<float2*>(outh + (size_t) R0   *128 + C0) = make_float2(h0,h1);
                *reinterpret_cast<float2*>(outh + (size_t)(R0+8)*128 + C0) = make_float2(h2,h3);
                *reinterpret_cast<float2*>(outc + (size_t) R0   *128 + C0) = make_float2(c0,c1);
                *reinterpret_cast<float2*>(outc + (size_t)(R0+8)*128 + C0) = make_float2(c2,c3);
            }
        }
    }
}

extern "C" void kernel_launch(void* const* d_in, const int* in_sizes, int n_in,
                              void* d_out, int out_size)
{
    const float* x       = (const float*)d_in[0];
    const float* child_h = (const float*)d_in[1];
    const float* child_c = (const float*)d_in[2];
    const float* Wi = (const float*)d_in[3];
    const float* bi = (const float*)d_in[4];
    const float* Ui = (const float*)d_in[5];
    const float* Wo = (const float*)d_in[6];
    const float* bo = (const float*)d_in[7];
    const float* Uo = (const float*)d_in[8];
    const float* Wu = (const float*)d_in[9];
    const float* bu = (const float*)d_in[10];
    const float* Uu = (const float*)d_in[11];
    const float* Wf = (const float*)d_in[12];
    const float* bf = (const float*)d_in[13];
    const float* Uf = (const float*)d_in[14];
    float* out = (float*)d_out;

    int N = in_sizes[0] / 128;
    int blocks = N / ROWS;

    prep_weights<<<8, 256>>>(Wf, Uf, Wu, Uu, Wi, Ui, Wo, Uo);

    cudaFuncSetAttribute(treelstm_kernel,
                         cudaFuncAttributeMaxDynamicSharedMemorySize, SMEM_BYTES);
    treelstm_kernel<<<blocks, THREADS, SMEM_BYTES>>>(
        x, child_h, child_c, bi, bo, bu, bf, out, N);
}

// round 6
// speedup vs baseline: 1.0026x; 1.0026x over previous
#include <cuda_runtime.h>
#include <cstdint>

#define LDA 132
#define THREADS 512
#define ROWS 64

// smem: hs(64) | Bt(64: x/cc/x) | CDw(128: Wf/Uf/U-gates) | EFw(128: child ping+pong / W-gates)
#define SMEM_FLOATS (384*LDA)
#define SMEM_BYTES  (SMEM_FLOATS*4)

__device__ float wbuf[8][128*LDA];   // pre-transposed, pre-rounded tf32 weights [n][k]

__device__ __forceinline__ float tf32r(float v){
    uint32_t u; asm("cvt.rna.tf32.f32 %0, %1;" : "=r"(u) : "f"(v));
    return __uint_as_float(u);
}
__device__ __forceinline__ float sigf(float v){
    float t = __expf(-v);
    return __fdividef(1.0f, 1.0f + t);
}
__device__ __forceinline__ float tanhfast(float v){
    v = fminf(fmaxf(v, -15.0f), 15.0f);
    float t = __expf(-2.0f*v);
    return __fdividef(1.0f - t, 1.0f + t);
}

__device__ __forceinline__ void cpa16(uint32_t s, const float* g){
    asm volatile("cp.async.cg.shared.global [%0], [%1], 16;\n" :: "r"(s), "l"(g));
}
#define CP_COMMIT() asm volatile("cp.async.commit_group;\n" ::: "memory")
#define CP_WAIT(n)  asm volatile("cp.async.wait_group %0;\n" :: "n"(n) : "memory")

template<int R>
__device__ __forceinline__ void cpa_tile(float* dst, const float* __restrict__ src,
                                         int rs, int tid){
    uint32_t base = (uint32_t)__cvta_generic_to_shared(dst);
    #pragma unroll
    for (int i=0;i<R*32/THREADS;i++){
        int e = tid + i*THREADS;
        int row = e >> 5;
        int c4  = (e & 31) * 4;
        cpa16(base + (uint32_t)(row*LDA + c4)*4u, src + (size_t)row*rs + c4);
    }
}

template<int R>
__device__ __forceinline__ void cvt_tile(float* t, int tid){
    #pragma unroll
    for (int i=0;i<R*32/THREADS;i++){
        int e = tid + i*THREADS;
        int row = e >> 5;
        int c4  = (e & 31) * 4;
        float4* p = reinterpret_cast<float4*>(t + row*LDA + c4);
        float4 v = *p;
        v.x=tf32r(v.x); v.y=tf32r(v.y); v.z=tf32r(v.z); v.w=tf32r(v.w);
        *p = v;
    }
}

__device__ __forceinline__ void cvt_child_accum(float* buf, float* hs, int tid){
    #pragma unroll
    for (int i=0;i<64*32/THREADS;i++){
        int e = tid + i*THREADS;
        int row = e >> 5;
        int c4  = (e & 31) * 4;
        float4* p = reinterpret_cast<float4*>(buf + row*LDA + c4);
        float4 v = *p;
        float4* hp = reinterpret_cast<float4*>(hs + row*LDA + c4);
        float4 h = *hp;
        h.x += v.x; h.y += v.y; h.z += v.z; h.w += v.w;
        *hp = h;
        v.x=tf32r(v.x); v.y=tf32r(v.y); v.z=tf32r(v.z); v.w=tf32r(v.w);
        *p = v;
    }
}

__device__ __forceinline__ void mma8(float* c, const uint32_t* a, const uint32_t* b){
    asm volatile(
      "mma.sync.aligned.m16n8k8.row.col.f32.tf32.tf32.f32 "
      "{%0,%1,%2,%3},{%4,%5,%6,%7},{%8,%9},{%0,%1,%2,%3};\n"
      : "+f"(c[0]), "+f"(c[1]), "+f"(c[2]), "+f"(c[3])
      : "r"(a[0]), "r"(a[1]), "r"(a[2]), "r"(a[3]),
        "r"(b[0]), "r"(b[1]));
}

__device__ __forceinline__ void ldsm4(uint32_t* d, uint32_t saddr){
    asm volatile("ldmatrix.sync.aligned.m8n8.x4.shared.b16 {%0,%1,%2,%3}, [%4];\n"
      : "=r"(d[0]),"=r"(d[1]),"=r"(d[2]),"=r"(d[3]) : "r"(saddr));
}

// 64x128x128 tf32 GEMM; 16 warps as 4(m) x 4(n); warp tile 16 x 32.
// A row-major [m][k], B transposed [n][k]; all frags via ldmatrix.
__device__ __forceinline__ void gemm64(float (&acc)[4][4],
                                       const float* __restrict__ As,
                                       const float* __restrict__ Bs,
                                       int lane, int wm, int wn)
{
    uint32_t abase = (uint32_t)__cvta_generic_to_shared(As);
    uint32_t bbase = (uint32_t)__cvta_generic_to_shared(Bs);
    int aRow = wm*16 + (lane&7) + ((lane>>3)&1)*8;
    int aCol = ((lane>>4)&1)*4;
    uint32_t aoff = abase + (uint32_t)(aRow*LDA + aCol)*4u;
    int bRow = wn*32 + (lane&7) + ((lane>>4)&1)*8;
    int bCol = ((lane>>3)&1)*4;
    uint32_t boff = bbase + (uint32_t)(bRow*LDA + bCol)*4u;

    #pragma unroll
    for (int k8=0;k8<16;k8++){
        uint32_t a[4], b[2][4];
        ldsm4(a,    aoff + k8*32u);
        ldsm4(b[0], boff + k8*32u);                 // nt 0,1
        ldsm4(b[1], boff + 16u*LDA*4u + k8*32u);    // nt 2,3
        mma8(acc[0], a, &b[0][0]);
        mma8(acc[1], a, &b[0][2]);
        mma8(acc[2], a, &b[1][0]);
        mma8(acc[3], a, &b[1][2]);
    }
}

#define ZERO_ACC(A) { _Pragma("unroll") for(int _n=0;_n<4;_n++) _Pragma("unroll") for(int _e=0;_e<4;_e++) (A)[_n][_e]=0.0f; }

// ---- prep: transpose + tf32-round all 8 weight matrices into wbuf ------
__global__ void prep_weights(const float* __restrict__ Wf, const float* __restrict__ Uf,
                             const float* __restrict__ Wu, const float* __restrict__ Uu,
                             const float* __restrict__ Wi, const float* __restrict__ Ui,
                             const float* __restrict__ Wo, const float* __restrict__ Uo)
{
    const float* srcs[8] = {Wf,Uf,Wu,Uu,Wi,Ui,Wo,Uo};
    const float* s = srcs[blockIdx.x];
    float* d = wbuf[blockIdx.x];
    for (int i = threadIdx.x; i < 128*128; i += blockDim.x){
        int n = i >> 7, k = i & 127;
        d[n*LDA + k] = tf32r(s[k*128 + n]);      // [n][k], tf32-rounded
    }
}

__global__ void __launch_bounds__(THREADS, 1)
treelstm_kernel(const float* __restrict__ x,
                const float* __restrict__ child_h,
                const float* __restrict__ child_c,
                const float* __restrict__ bi, const float* __restrict__ bo,
                const float* __restrict__ bu, const float* __restrict__ bf,
                float* __restrict__ out, int N)
{
    extern __shared__ float smem[];
    float* hsA  = smem;               // 64 rows : h_sum (fp32 -> tf32)
    float* Bt   = smem + 64*LDA;      // 64 rows : x tile / child_c / x tile
    float* CDw  = smem + 128*LDA;     // 128 rows: Wf / Uf / U-gates
    float* EFw  = smem + 256*LDA;     // 128 rows: child ping+pong / W-gates
    float* bufA = EFw;
    float* bufB = EFw + 64*LDA;

    const int tid  = threadIdx.x;
    const int lane = tid & 31;
    const int g    = lane >> 2;
    const int r    = lane & 3;
    const int wid  = tid >> 5;
    const int wm   = wid & 3;        // 4 m-groups of 16 rows
    const int wn   = wid >> 2;       // 4 n-groups of 32 cols
    const int m0   = blockIdx.x * ROWS;

    float acc [4][4];
    float cacc[4][4];
    float aux [4][4];

    // ---- prologue ------------------------------------------------------
    cpa_tile<64 >(Bt,  x + (size_t)m0*128, 128, tid);
    cpa_tile<128>(CDw, wbuf[0], LDA, tid);                 // Wf (ready-to-use)
    CP_COMMIT();                                           // G1
    cpa_tile<64>(bufA, child_h + ((size_t)m0*8 + 0)*128, 8*128, tid);
    CP_COMMIT();                                           // G2
    cpa_tile<64>(bufB, child_h + ((size_t)m0*8 + 1)*128, 8*128, tid);
    CP_COMMIT();                                           // G3

    #pragma unroll
    for (int i=0;i<64*32/THREADS;i++){
        int e = tid + i*THREADS;
        int row = e>>5, c4=(e&31)*4;
        *reinterpret_cast<float4*>(hsA + row*LDA + c4) = make_float4(0.f,0.f,0.f,0.f);
    }

    CP_WAIT(2); __syncthreads();                           // x + Wf
    cvt_tile<64>(Bt, tid);
    __syncthreads();

    // ---- phase 1: xf = x @ Wf + bf -------------------------------------
    ZERO_ACC(acc);
    gemm64(acc, Bt, CDw, lane, wm, wn);
    __syncthreads();                                       // Bt, CDw free
    cpa_tile<128>(CDw, wbuf[1], LDA, tid);                 // Uf
    CP_COMMIT();                                           // G4

    #pragma unroll
    for (int nt=0;nt<4;nt++){
        int C0 = wn*32 + nt*8 + 2*r;
        float2 bv = *reinterpret_cast<const float2*>(bf + C0);
        aux[nt][0] = acc[nt][0] + bv.x;
        aux[nt][1] = acc[nt][1] + bv.y;
        aux[nt][2] = acc[nt][2] + bv.x;
        aux[nt][3] = acc[nt][3] + bv.y;
        cacc[nt][0]=0.f; cacc[nt][1]=0.f; cacc[nt][2]=0.f; cacc[nt][3]=0.f;
    }

    // ---- phase 2: children ---------------------------------------------
    for (int k=0;k<8;k++){
        float* buf = (k&1) ? bufB : bufA;
        CP_WAIT(0);                                        // ch_k (+Uf at k=0)
        __syncthreads();                                   // (a) prev epilogue done
        cvt_child_accum(buf, hsA, tid);
        cpa_tile<64>(Bt, child_c + ((size_t)m0*8 + k)*128, 8*128, tid);
        CP_COMMIT();
        if (k<7){
            float* nbuf = (k&1) ? bufA : bufB;
            cpa_tile<64>(nbuf, child_h + ((size_t)m0*8 + (k+1))*128, 8*128, tid);
            CP_COMMIT();
        }
        __syncthreads();                                   // (b) cvt visible
        ZERO_ACC(acc);
        gemm64(acc, buf, CDw, lane, wm, wn);
        if (k<7) { CP_WAIT(1); } else { CP_WAIT(0); }      // cc_k done
        __syncthreads();                                   // (c) cc visible
        #pragma unroll
        for (int nt=0;nt<4;nt++){
            int Rr = wm*16 + g;
            int C0 = wn*32 + nt*8 + 2*r;
            float2 c0 = *reinterpret_cast<const float2*>(Bt +  Rr   *LDA + C0);
            float2 c1 = *reinterpret_cast<const float2*>(Bt + (Rr+8)*LDA + C0);
            cacc[nt][0] += sigf(aux[nt][0] + acc[nt][0]) * c0.x;
            cacc[nt][1] += sigf(aux[nt][1] + acc[nt][1]) * c0.y;
            cacc[nt][2] += sigf(aux[nt][2] + acc[nt][2]) * c1.x;
            cacc[nt][3] += sigf(aux[nt][3] + acc[nt][3]) * c1.y;
        }
    }

    __syncthreads();                                       // all bufs free
    cvt_tile<64>(hsA, tid);                                // round h_sum (own elems)
    cpa_tile<64 >(Bt,  x + (size_t)m0*128, 128, tid);      // x reload
    cpa_tile<128>(EFw, wbuf[2], LDA, tid);                 // Wu
    CP_COMMIT();                                           // G: x+Wu
    cpa_tile<128>(CDw, wbuf[3], LDA, tid);                 // Uu
    CP_COMMIT();                                           // G: Uu

    const float* bs[3] = {bu, bi, bo};

    // ---- phase 3: gates u, i, o ----------------------------------------
    for (int gate=0; gate<3; gate++){
        CP_WAIT(1); __syncthreads();                       // W_gate (+x at gate0)
        if (gate==0){ cvt_tile<64>(Bt, tid); __syncthreads(); }
        ZERO_ACC(acc);
        gemm64(acc, Bt, EFw, lane, wm, wn);
        __syncthreads();                                   // EFw free
        if (gate<2){ cpa_tile<128>(EFw, wbuf[4 + 2*gate], LDA, tid); CP_COMMIT(); }

        if (gate<2) { CP_WAIT(1); } else { CP_WAIT(0); }   // U_gate
        __syncthreads();
        gemm64(acc, hsA, CDw, lane, wm, wn);
        __syncthreads();                                   // CDw free
        if (gate<2){ cpa_tile<128>(CDw, wbuf[5 + 2*gate], LDA, tid); CP_COMMIT(); }

        const float* bp = bs[gate];
        #pragma unroll
        for (int nt=0;nt<4;nt++){
            int C0 = wn*32 + nt*8 + 2*r;
            float2 bv = *reinterpret_cast<const float2*>(bp + C0);
            float p0 = acc[nt][0] + bv.x;
            float p1 = acc[nt][1] + bv.y;
            float p2 = acc[nt][2] + bv.x;
            float p3 = acc[nt][3] + bv.y;
            if (gate == 0){
                aux[nt][0] = tanhfast(p0);
                aux[nt][1] = tanhfast(p1);
                aux[nt][2] = tanhfast(p2);
                aux[nt][3] = tanhfast(p3);
            } else if (gate == 1){
                cacc[nt][0] += sigf(p0) * aux[nt][0];
                cacc[nt][1] += sigf(p1) * aux[nt][1];
                cacc[nt][2] += sigf(p2) * aux[nt][2];
                cacc[nt][3] += sigf(p3) * aux[nt][3];
            } else {
                int R0 = m0 + wm*16 + g;
                float c0 = cacc[nt][0], c1 = cacc[nt][1];
                float c2 = cacc[nt][2], c3 = cacc[nt][3];
                float h0 = sigf(p0) * tanhfast(c0);
                float h1 = sigf(p1) * tanhfast(c1);
                float h2 = sigf(p2) * tanhfast(c2);
                float h3 = sigf(p3) * tanhfast(c3);
                float* outh = out;
                float* outc = out + (size_t)N*128;
                *reinterpret_cast<float2*>(outh + (size_t) R0   *128 + C0) = make_float2(h0,h1);
                *reinterpret_cast<float2*>(outh + (size_t)(R0+8)*128 + C0) = make_float2(h2,h3);
                *reinterpret_cast<float2*>(outc + (size_t) R0   *128 + C0) = make_float2(c0,c1);
                *reinterpret_cast<float2*>(outc + (size_t)(R0+8)*128 + C0) = make_float2(c2,c3);
            }
        }
    }
}

extern "C" void kernel_launch(void* const* d_in, const int* in_sizes, int n_in,
                              void* d_out, int out_size)
{
    const float* x       = (const float*)d_in[0];
    const float* child_h = (const float*)d_in[1];
    const float* child_c = (const float*)d_in[2];
    const float* Wi = (const float*)d_in[3];
    const float* bi = (const float*)d_in[4];
    const float* Ui = (const float*)d_in[5];
    const float* Wo = (const float*)d_in[6];
    const float* bo = (const float*)d_in[7];
    const float* Uo = (const float*)d_in[8];
    const float* Wu = (const float*)d_in[9];
    const float* bu = (const float*)d_in[10];
    const float* Uu = (const float*)d_in[11];
    const float* Wf = (const float*)d_in[12];
    const float* bf = (const float*)d_in[13];
    const float* Uf = (const float*)d_in[14];
    float* out = (float*)d_out;

    int N = in_sizes[0] / 128;
    int blocks = N / ROWS;

    prep_weights<<<8, 256>>>(Wf, Uf, Wu, Uu, Wi, Ui, Wo, Uo);

    cudaFuncSetAttribute(treelstm_kernel,
                         cudaFuncAttributeMaxDynamicSharedMemorySize, SMEM_BYTES);
    treelstm_kernel<<<blocks, THREADS, SMEM_BYTES>>>(
        x, child_h, child_c, bi, bo, bu, bf, out, N);
}

// round 11
// speedup vs baseline: 1.1302x; 1.1272x over previous
#include <cuda_runtime.h>
#include <cstdint>

#define LDA 132
#define THREADS 256
#define ROWS 64

// rows: A(64: x resident) | B(64) C(64) D(64): child rotation / hs / gate-W ping | W(128)
#define SMEM_FLOATS (384*LDA)
#define SMEM_BYTES  (SMEM_FLOATS*4)

__device__ float wbuf[8][128*LDA];   // pre-transposed, pre-rounded tf32 weights [n][k]

__device__ __forceinline__ float tf32r(float v){
    uint32_t u; asm("cvt.rna.tf32.f32 %0, %1;" : "=r"(u) : "f"(v));
    return __uint_as_float(u);
}
__device__ __forceinline__ float sigf(float v){
    float t = __expf(-v);
    return __fdividef(1.0f, 1.0f + t);
}
__device__ __forceinline__ float tanhfast(float v){
    v = fminf(fmaxf(v, -15.0f), 15.0f);
    float t = __expf(-2.0f*v);
    return __fdividef(1.0f - t, 1.0f + t);
}

__device__ __forceinline__ void cpa16(uint32_t s, const float* g){
    asm volatile("cp.async.cg.shared.global [%0], [%1], 16;\n" :: "r"(s), "l"(g));
}
#define CP_COMMIT() asm volatile("cp.async.commit_group;\n" ::: "memory")
#define CP_WAIT(n)  asm volatile("cp.async.wait_group %0;\n" :: "n"(n) : "memory")

template<int R>
__device__ __forceinline__ void cpa_tile(float* dst, const float* __restrict__ src,
                                         int rs, int tid){
    uint32_t base = (uint32_t)__cvta_generic_to_shared(dst);
    #pragma unroll
    for (int i=0;i<R*32/THREADS;i++){
        int e = tid + i*THREADS;
        int row = e >> 5;
        int c4  = (e & 31) * 4;
        cpa16(base + (uint32_t)(row*LDA + c4)*4u, src + (size_t)row*rs + c4);
    }
}

template<int R>
__device__ __forceinline__ void cvt_tile(float* t, int tid){
    #pragma unroll
    for (int i=0;i<R*32/THREADS;i++){
        int e = tid + i*THREADS;
        int row = e >> 5;
        int c4  = (e & 31) * 4;
        float4* p = reinterpret_cast<float4*>(t + row*LDA + c4);
        float4 v = *p;
        v.x=tf32r(v.x); v.y=tf32r(v.y); v.z=tf32r(v.z); v.w=tf32r(v.w);
        *p = v;
    }
}

__device__ __forceinline__ void mma8(float* c, const uint32_t* a, const uint32_t* b){
    asm volatile(
      "mma.sync.aligned.m16n8k8.row.col.f32.tf32.tf32.f32 "
      "{%0,%1,%2,%3},{%4,%5,%6,%7},{%8,%9},{%0,%1,%2,%3};\n"
      : "+f"(c[0]), "+f"(c[1]), "+f"(c[2]), "+f"(c[3])
      : "r"(a[0]), "r"(a[1]), "r"(a[2]), "r"(a[3]),
        "r"(b[0]), "r"(b[1]));
}

__device__ __forceinline__ void ldsm4(uint32_t* d, uint32_t saddr){
    asm volatile("ldmatrix.sync.aligned.m8n8.x4.shared.b16 {%0,%1,%2,%3}, [%4];\n"
      : "=r"(d[0]),"=r"(d[1]),"=r"(d[2]),"=r"(d[3]) : "r"(saddr));
}

// 64x128x128 tf32 GEMM; 8 warps as 2(m) x 4(n); warp tile 32 x 32.
// A row-major [m][k], B transposed [n][k]; all frags via ldmatrix.
__device__ __forceinline__ void gemm64(float (&acc)[2][4][4],
                                       const float* __restrict__ As,
                                       const float* __restrict__ Bs,
                                       int lane, int wm, int wn)
{
    uint32_t abase = (uint32_t)__cvta_generic_to_shared(As);
    uint32_t bbase = (uint32_t)__cvta_generic_to_shared(Bs);
    int aRow = wm*32 + (lane&7) + ((lane>>3)&1)*8;
    int aCol = ((lane>>4)&1)*4;
    uint32_t aoff = abase + (uint32_t)(aRow*LDA + aCol)*4u;
    int bRow = wn*32 + (lane&7) + ((lane>>4)&1)*8;
    int bCol = ((lane>>3)&1)*4;
    uint32_t boff = bbase + (uint32_t)(bRow*LDA + bCol)*4u;

    #pragma unroll
    for (int k8=0;k8<16;k8++){
        uint32_t a[2][4], b[2][4];
        ldsm4(a[0], aoff + k8*32u);
        ldsm4(a[1], aoff + 16u*LDA*4u + k8*32u);
        ldsm4(b[0], boff + k8*32u);                 // nt 0,1
        ldsm4(b[1], boff + 16u*LDA*4u + k8*32u);    // nt 2,3
        #pragma unroll
        for (int mt=0; mt<2; mt++){
            mma8(acc[mt][0], a[mt], &b[0][0]);
            mma8(acc[mt][1], a[mt], &b[0][2]);
            mma8(acc[mt][2], a[mt], &b[1][0]);
            mma8(acc[mt][3], a[mt], &b[1][2]);
        }
    }
}

#define ZERO_ACC(A) { _Pragma("unroll") for(int _m=0;_m<2;_m++) _Pragma("unroll") for(int _n=0;_n<4;_n++) _Pragma("unroll") for(int _e=0;_e<4;_e++) (A)[_m][_n][_e]=0.0f; }

// ---- prep: transpose + tf32-round all 8 weight matrices into wbuf ------
__global__ void prep_weights(const float* __restrict__ Wf, const float* __restrict__ Uf,
                             const float* __restrict__ Wu, const float* __restrict__ Uu,
                             const float* __restrict__ Wi, const float* __restrict__ Ui,
                             const float* __restrict__ Wo, const float* __restrict__ Uo)
{
    const float* srcs[8] = {Wf,Uf,Wu,Uu,Wi,Ui,Wo,Uo};
    const float* s = srcs[blockIdx.x];
    float* d = wbuf[blockIdx.x];
    for (int i = threadIdx.x; i < 128*128; i += blockDim.x){
        int n = i >> 7, k = i & 127;
        d[n*LDA + k] = tf32r(s[k*128 + n]);      // [n][k], tf32-rounded
    }
}

__global__ void __launch_bounds__(THREADS, 1)
treelstm_kernel(const float* __restrict__ x,
                const float* __restrict__ child_h,
                const float* __restrict__ child_c,
                const float* __restrict__ bi, const float* __restrict__ bo,
                const float* __restrict__ bu, const float* __restrict__ bf,
                float* __restrict__ out, int N)
{
    extern __shared__ float smem[];
    float* At  = smem;                 // 64 rows : x tile (tf32), resident entire kernel
    float* Bt  = smem +  64*LDA;       // 64 rows : child rot 0 / hs (gate phase)
    float* Ct  = smem + 128*LDA;       // 64 rows : child rot 1 \ gate-W ping (128 rows)
    float* Dt  = smem + 192*LDA;       // 64 rows : child rot 2 /
    float* Wt  = smem + 256*LDA;       // 128 rows: Wf / Uf / U-gates (pong)
    float* CDw = Ct;                   // 128-row alias for gate W ping

    const int tid  = threadIdx.x;
    const int lane = tid & 31;
    const int g    = lane >> 2;
    const int r    = lane & 3;
    const int wid  = tid >> 5;
    const int wm   = wid & 1;
    const int wn   = wid >> 1;
    const int m0   = blockIdx.x * ROWS;

    const int Rr0 = wm*32 + g;          // owned rows: Rr0+mt*16, Rr0+mt*16+8
    float acc [2][4][4];
    float cacc[2][4][4];
    float xfv [2][4][4];                // xf during child loop, then u
    float hs  [2][4][4];                // h_sum accumulator (registers)

    // ---- prologue: x->A + Wf->W | ch0->B | ch1->C ----------------------
    cpa_tile<64 >(At, x + (size_t)m0*128, 128, tid);
    cpa_tile<128>(Wt, wbuf[0], LDA, tid);
    CP_COMMIT();                                           // G1
    cpa_tile<64>(Bt, child_h + ((size_t)m0*8 + 0)*128, 8*128, tid);
    CP_COMMIT();                                           // G2
    cpa_tile<64>(Ct, child_h + ((size_t)m0*8 + 1)*128, 8*128, tid);
    CP_COMMIT();                                           // G3

    #pragma unroll
    for (int mt=0;mt<2;mt++)
      #pragma unroll
      for (int nt=0;nt<4;nt++)
        #pragma unroll
        for (int e=0;e<4;e++){ hs[mt][nt][e]=0.f; cacc[mt][nt][e]=0.f; }

    CP_WAIT(2); __syncthreads();                           // x + Wf ready
    cvt_tile<64>(At, tid);                                 // round x (stays rounded)
    __syncthreads();

    // ---- phase 1: xf = x @ Wf + bf -------------------------------------
    ZERO_ACC(acc);
    gemm64(acc, At, Wt, lane, wm, wn);
    __syncthreads();                                       // Wt free
    cpa_tile<128>(Wt, wbuf[1], LDA, tid);                  // Uf
    CP_COMMIT();                                           // G4
    cpa_tile<64>(Dt, child_h + ((size_t)m0*8 + 2)*128, 8*128, tid);
    CP_COMMIT();                                           // G5

    #pragma unroll
    for (int mt=0;mt<2;mt++)
      #pragma unroll
      for (int nt=0;nt<4;nt++){
        int C0 = wn*32 + nt*8 + 2*r;
        float2 bv = *reinterpret_cast<const float2*>(bf + C0);
        xfv[mt][nt][0] = acc[mt][nt][0] + bv.x;
        xfv[mt][nt][1] = acc[mt][nt][1] + bv.y;
        xfv[mt][nt][2] = acc[mt][nt][2] + bv.x;
        xfv[mt][nt][3] = acc[mt][nt][3] + bv.y;
      }

    // ---- phase 2: children (3-deep rotation over B,C,D; Uf resident) ---
    float* bufs[3] = {Bt, Ct, Dt};
    for (int k=0;k<8;k++){
        float* buf = bufs[k%3];
        if (k==0) { CP_WAIT(1); }                          // Uf + ch0 + ch1 ready
        else      { CP_WAIT(2); }                          // ch_k ready
        __syncthreads();

        // hs += own slice of raw child tile (LDS.64 x16, no STS)
        #pragma unroll
        for (int mt=0;mt<2;mt++)
          #pragma unroll
          for (int nt=0;nt<4;nt++){
            int Rr = Rr0 + mt*16;
            int C0 = wn*32 + nt*8 + 2*r;
            float2 v0 = *reinterpret_cast<const float2*>(buf +  Rr   *LDA + C0);
            float2 v1 = *reinterpret_cast<const float2*>(buf + (Rr+8)*LDA + C0);
            hs[mt][nt][0] += v0.x; hs[mt][nt][1] += v0.y;
            hs[mt][nt][2] += v1.x; hs[mt][nt][3] += v1.y;
          }

        // F_k = ch_k (raw fp32 -> tf32 truncation in HW) @ Uf
        ZERO_ACC(acc);
        gemm64(acc, buf, Wt, lane, wm, wn);

        // child_c direct from global, combine
        #pragma unroll
        for (int mt=0;mt<2;mt++)
          #pragma unroll
          for (int nt=0;nt<4;nt++){
            int Rm = m0 + Rr0 + mt*16;
            int C0 = wn*32 + nt*8 + 2*r;
            float2 c0 = __ldg(reinterpret_cast<const float2*>(child_c + ((size_t)Rm    *8 + k)*128 + C0));
            float2 c1 = __ldg(reinterpret_cast<const float2*>(child_c + ((size_t)(Rm+8)*8 + k)*128 + C0));
            cacc[mt][nt][0] += sigf(xfv[mt][nt][0] + acc[mt][nt][0]) * c0.x;
            cacc[mt][nt][1] += sigf(xfv[mt][nt][1] + acc[mt][nt][1]) * c0.y;
            cacc[mt][nt][2] += sigf(xfv[mt][nt][2] + acc[mt][nt][2]) * c1.x;
            cacc[mt][nt][3] += sigf(xfv[mt][nt][3] + acc[mt][nt][3]) * c1.y;
          }

        __syncthreads();                                   // all reads of buf done
        if (k+3 < 8){
            cpa_tile<64>(buf, child_h + ((size_t)m0*8 + (k+3))*128, 8*128, tid);
            CP_COMMIT();
        }
    }

    // ---- gate prologue: hs -> Bt (tf32), weights ping-pong --------------
    #pragma unroll
    for (int mt=0;mt<2;mt++)
      #pragma unroll
      for (int nt=0;nt<4;nt++){
        int Rr = Rr0 + mt*16;
        int C0 = wn*32 + nt*8 + 2*r;
        *reinterpret_cast<float2*>(Bt +  Rr   *LDA + C0) =
            make_float2(tf32r(hs[mt][nt][0]), tf32r(hs[mt][nt][1]));
        *reinterpret_cast<float2*>(Bt + (Rr+8)*LDA + C0) =
            make_float2(tf32r(hs[mt][nt][2]), tf32r(hs[mt][nt][3]));
      }
    cpa_tile<128>(CDw, wbuf[2], LDA, tid); CP_COMMIT();    // Wu (ping = C+D)
    cpa_tile<128>(Wt , wbuf[3], LDA, tid); CP_COMMIT();    // Uu (pong)

    const float* bs[3] = {bu, bi, bo};

    // ---- phase 3: gates u, i, o ----------------------------------------
    for (int gate=0; gate<3; gate++){
        CP_WAIT(1); __syncthreads();                       // W_gate ready (hs STS also visible)
        ZERO_ACC(acc);
        gemm64(acc, At, CDw, lane, wm, wn);                // x @ W_g
        __syncthreads();                                   // ping free
        if (gate<2){ cpa_tile<128>(CDw, wbuf[4 + 2*gate], LDA, tid); CP_COMMIT(); }

        if (gate<2) { CP_WAIT(1); } else { CP_WAIT(0); }   // U_gate ready
        __syncthreads();
        gemm64(acc, Bt, Wt, lane, wm, wn);                 // + hs @ U_g
        __syncthreads();                                   // pong free
        if (gate<2){ cpa_tile<128>(Wt, wbuf[5 + 2*gate], LDA, tid); CP_COMMIT(); }

        const float* bp = bs[gate];
        #pragma unroll
        for (int mt=0;mt<2;mt++)
          #pragma unroll
          for (int nt=0;nt<4;nt++){
            int C0 = wn*32 + nt*8 + 2*r;
            float2 bv = *reinterpret_cast<const float2*>(bp + C0);
            float p0 = acc[mt][nt][0] + bv.x;
            float p1 = acc[mt][nt][1] + bv.y;
            float p2 = acc[mt][nt][2] + bv.x;
            float p3 = acc[mt][nt][3] + bv.y;
            if (gate == 0){                                // u = tanh(.)
                xfv[mt][nt][0] = tanhfast(p0);
                xfv[mt][nt][1] = tanhfast(p1);
                xfv[mt][nt][2] = tanhfast(p2);
                xfv[mt][nt][3] = tanhfast(p3);
            } else if (gate == 1){                         // c += sig(i)*u
                cacc[mt][nt][0] += sigf(p0) * xfv[mt][nt][0];
                cacc[mt][nt][1] += sigf(p1) * xfv[mt][nt][1];
                cacc[mt][nt][2] += sigf(p2) * xfv[mt][nt][2];
                cacc[mt][nt][3] += sigf(p3) * xfv[mt][nt][3];
            } else {                                       // o: write h, c
                int R0 = m0 + Rr0 + mt*16;
                float c0 = cacc[mt][nt][0], c1 = cacc[mt][nt][1];
                float c2 = cacc[mt][nt][2], c3 = cacc[mt][nt][3];
                float h0 = sigf(p0) * tanhfast(c0);
                float h1 = sigf(p1) * tanhfast(c1);
                float h2 = sigf(p2) * tanhfast(c2);
                float h3 = sigf(p3) * tanhfast(c3);
                float* outh = out;
                float* outc = out + (size_t)N*128;
                *reinterpret_cast<float2*>(outh + (size_t) R0   *128 + C0) = make_float2(h0,h1);
                *reinterpret_cast<float2*>(outh + (size_t)(R0+8)*128 + C0) = make_float2(h2,h3);
                *reinterpret_cast<float2*>(outc + (size_t) R0   *128 + C0) = make_float2(c0,c1);
                *reinterpret_cast<float2*>(outc + (size_t)(R0+8)*128 + C0) = make_float2(c2,c3);
            }
          }
    }
}

extern "C" void kernel_launch(void* const* d_in, const int* in_sizes, int n_in,
                              void* d_out, int out_size)
{
    const float* x       = (const float*)d_in[0];
    const float* child_h = (const float*)d_in[1];
    const float* child_c = (const float*)d_in[2];
    const float* Wi = (const float*)d_in[3];
    const float* bi = (const float*)d_in[4];
    const float* Ui = (const float*)d_in[5];
    const float* Wo = (const float*)d_in[6];
    const float* bo = (const float*)d_in[7];
    const float* Uo = (const float*)d_in[8];
    const float* Wu = (const float*)d_in[9];
    const float* bu = (const float*)d_in[10];
    const float* Uu = (const float*)d_in[11];
    const float* Wf = (const float*)d_in[12];
    const float* bf = (const float*)d_in[13];
    const float* Uf = (const float*)d_in[14];
    float* out = (float*)d_out;

    int N = in_sizes[0] / 128;
    int blocks = N / ROWS;

    prep_weights<<<8, 256>>>(Wf, Uf, Wu, Uu, Wi, Ui, Wo, Uo);

    cudaFuncSetAttribute(treelstm_kernel,
                         cudaFuncAttributeMaxDynamicSharedMemorySize, SMEM_BYTES);
    treelstm_kernel<<<blocks, THREADS, SMEM_BYTES>>>(
        x, child_h, child_c, bi, bo, bu, bf, out, N);
}